// round 11
// baseline (speedup 1.0000x reference)
#include <cuda_runtime.h>
#include <cstdint>

// WKV (RWKV v4) — warp-parallel weighted scan over T. Single pass:
// k,v read once, y written once (192 MB = traffic floor). No segmentation,
// no inter-block sync.
//
//   state_t = lam*state_{t-1} + e^{k_t}(v_t, 1),  lam = exp(-exp(td[c]))
//   y_t = (A_{t-1} + e^u e^{k_t} v_t) / (B_{t-1} + e^u e^{k_t})
//
// Key identity: per-channel decay lam is constant, so the inclusive decayed
// prefix  incl(l) = sum_{i<=l} lam^{l-i} u_i  is a Kogge-Stone scan with
// lane-uniform weights lam^{2^j} (5 shfl levels, 2 fmas each).
//   A_pre(l) = lam^l * S + incl(l-1)      (S = seed at chunk start)
//   S'       = lam^32 * S + incl(31)      (1 broadcast + 1 fma per chunk)
//
// Mapping: block = 512 thr = 16 warps = 16 channels x full T; warp = one
// channel, lane = timestep-within-chunk. k/v tiles (128 t x 16 c) are
// transposed through smem (row stride 17 -> conflict-free column LDS),
// loaded with 4B cp.async (rows are 64B contiguous = full sectors),
// double-buffered. y staged in smem, flushed with coalesced .cs stores.

constexpr int CPB     = 16;          // channels per block == warps
constexpr int TS      = 128;         // timesteps per tile
constexpr int STR     = CPB + 1;     // smem row stride (17 floats)
constexpr int THREADS = CPB * 32;    // 512
constexpr int GRID    = 1024;        // B*C/CPB for the expected shape
constexpr int LD_IT   = (TS * CPB) / THREADS;   // 4 elements/thread/array
constexpr int TILE_F  = TS * STR;    // floats per tile buffer
// smem: k[2][TILE_F] | v[2][TILE_F] | y[2][TILE_F]
constexpr int SMEM_BYTES = 6 * TILE_F * (int)sizeof(float);  // 52224 B

__device__ __forceinline__ void cpasync4(float* s, const float* g) {
    unsigned sa = (unsigned)__cvta_generic_to_shared(s);
    asm volatile("cp.async.ca.shared.global [%0], [%1], 4;\n"
                 :: "r"(sa), "l"(g) : "memory");
}

__device__ __forceinline__ void stcs(float* p, float v) {
    asm volatile("st.global.cs.f32 [%0], %1;\n" :: "l"(p), "f"(v) : "memory");
}

__device__ __forceinline__ int read_dim(const void* p) {
    int i = *reinterpret_cast<const int*>(p);
    if (i >= 1 && i <= (1 << 20)) return i;
    float f = *reinterpret_cast<const float*>(p);
    int fi = (int)f;
    return (fi >= 1) ? fi : 1;
}

__global__ __launch_bounds__(THREADS, 2)
void wkv_warpscan_kernel(const void* __restrict__ seqlen_p,
                         const float* __restrict__ td,
                         const float* __restrict__ tf,
                         const float* __restrict__ kg,
                         const float* __restrict__ vg,
                         float* __restrict__ out,
                         int C, long long BTC)
{
    extern __shared__ float smem[];
    float* sk = smem;                 // [2][TILE_F]
    float* sv = smem + 2 * TILE_F;    // [2][TILE_F]
    float* sy = smem + 4 * TILE_F;    // [2][TILE_F]

    const int tid  = threadIdx.x;
    const int w    = tid >> 5;        // warp == local channel
    const int lane = tid & 31;

    const int T = read_dim(seqlen_p);
    const long long BT = BTC / C;
    const int B = (int)(BT / T);
    const int ctiles = (C + CPB - 1) / CPB;
    const int nrows  = B * ctiles;
    const int ntiles = (T + TS - 1) / TS;
    const unsigned FULL = 0xffffffffu;

    for (int row = blockIdx.x; row < nrows; row += gridDim.x) {
        const int b  = row / ctiles;
        const int c0 = (row % ctiles) * CPB;
        const float* kb = kg + (long long)b * T * C;
        const float* vb = vg + (long long)b * T * C;
        float* ob = out + (long long)b * T * C;

        // Per-channel constants (warp-uniform).
        const int  c      = c0 + w;
        const bool cvalid = (c < C);
        const float ew  = cvalid ? __expf(td[c]) : 0.f;   // e^{td}
        const float eu  = cvalid ? __expf(tf[c]) : 0.f;   // e^{tf}
        const float lam = __expf(-ew);                    // exp(-e^{td})
        const float lam2  = lam  * lam;
        const float lam4  = lam2 * lam2;
        const float lam8  = lam4 * lam4;
        const float lam16 = lam8 * lam8;
        const float lam32 = lam16 * lam16;
        const float lamlane = __expf(-(float)lane * ew);  // lam^lane

        float SA = 0.f, SB = 0.f;                         // running seed

        auto load_tile = [&](int ti) {
            if (ti < ntiles) {
                const int buf = ti & 1;
                const int t0  = ti * TS;
                #pragma unroll
                for (int i = 0; i < LD_IT; ++i) {
                    const int idx = tid + i * THREADS;
                    const int t  = idx / CPB;
                    const int cc = idx % CPB;
                    const int gt = t0 + t;
                    const int gc = c0 + cc;
                    float* dk = &sk[buf * TILE_F + t * STR + cc];
                    float* dv = &sv[buf * TILE_F + t * STR + cc];
                    if (gt < T && gc < C) {
                        const long long go = (long long)gt * C + gc;
                        cpasync4(dk, kb + go);
                        cpasync4(dv, vb + go);
                    } else {
                        *dk = 0.f; *dv = 0.f;
                    }
                }
            }
            asm volatile("cp.async.commit_group;\n" ::);
        };

        load_tile(0);
        load_tile(1);

        for (int ti = 0; ti < ntiles; ++ti) {
            const int buf = ti & 1;
            asm volatile("cp.async.wait_group 1;\n" ::);
            __syncthreads();

            const float* tk = &sk[buf * TILE_F];
            const float* tv = &sv[buf * TILE_F];
            float*       ty = &sy[buf * TILE_F];
            const int t0    = ti * TS;
            const int steps = min(TS, T - t0);

            #pragma unroll
            for (int m = 0; m < TS / 32; ++m) {
                if (m * 32 < steps) {            // warp-uniform
                    const int t = m * 32 + lane;
                    const bool tvld = (t0 + t) < T;
                    const float kt = tk[t * STR + w];
                    const float vt = tv[t * STR + w];
                    const float ek = tvld ? __expf(kt) : 0.f;
                    float uA = ek * vt;
                    float uB = ek;

                    // Weighted Kogge-Stone inclusive scan.
                    float a, bsh;
                    a   = __shfl_up_sync(FULL, uA, 1);
                    bsh = __shfl_up_sync(FULL, uB, 1);
                    if (lane >= 1)  { uA = fmaf(lam,   a, uA); uB = fmaf(lam,   bsh, uB); }
                    a   = __shfl_up_sync(FULL, uA, 2);
                    bsh = __shfl_up_sync(FULL, uB, 2);
                    if (lane >= 2)  { uA = fmaf(lam2,  a, uA); uB = fmaf(lam2,  bsh, uB); }
                    a   = __shfl_up_sync(FULL, uA, 4);
                    bsh = __shfl_up_sync(FULL, uB, 4);
                    if (lane >= 4)  { uA = fmaf(lam4,  a, uA); uB = fmaf(lam4,  bsh, uB); }
                    a   = __shfl_up_sync(FULL, uA, 8);
                    bsh = __shfl_up_sync(FULL, uB, 8);
                    if (lane >= 8)  { uA = fmaf(lam8,  a, uA); uB = fmaf(lam8,  bsh, uB); }
                    a   = __shfl_up_sync(FULL, uA, 16);
                    bsh = __shfl_up_sync(FULL, uB, 16);
                    if (lane >= 16) { uA = fmaf(lam16, a, uA); uB = fmaf(lam16, bsh, uB); }

                    // Exclusive local prefix, then add decayed seed.
                    float Aex = __shfl_up_sync(FULL, uA, 1);
                    float Bex = __shfl_up_sync(FULL, uB, 1);
                    if (lane == 0) { Aex = 0.f; Bex = 0.f; }
                    const float Apre = fmaf(lamlane, SA, Aex);
                    const float Bpre = fmaf(lamlane, SB, Bex);

                    const float eku = eu * ek;
                    const float y = __fdividef(fmaf(eku, vt, Apre), Bpre + eku);
                    ty[t * STR + w] = y;

                    // Seed for next chunk.
                    const float LA = __shfl_sync(FULL, uA, 31);
                    const float LB = __shfl_sync(FULL, uB, 31);
                    SA = fmaf(lam32, SA, LA);
                    SB = fmaf(lam32, SB, LB);
                }
            }
            __syncthreads();     // tile buffers free, y staged

            load_tile(ti + 2);   // refill the buffer we just consumed

            // Coalesced flush of staged y.
            #pragma unroll
            for (int i = 0; i < LD_IT; ++i) {
                const int idx = tid + i * THREADS;
                const int t  = idx / CPB;
                const int cc = idx % CPB;
                const int gt = t0 + t;
                const int gc = c0 + cc;
                if (gt < T && gc < C)
                    stcs(ob + (long long)gt * C + gc, ty[t * STR + cc]);
            }
        }
        asm volatile("cp.async.wait_group 0;\n" ::);
        __syncthreads();
    }
}

extern "C" void kernel_launch(void* const* d_in, const int* in_sizes, int n_in,
                              void* d_out, int out_size)
{
    // metadata order: batch_size, seq_len, embedding_dim, time_decay,
    //                 time_first, k, v
    const void*  seqlen_p = d_in[1];
    const float* td = (const float*)d_in[3];
    const float* tf = (const float*)d_in[4];
    const float* k  = (const float*)d_in[5];
    const float* v  = (const float*)d_in[6];
    float* out = (float*)d_out;

    const int C = in_sizes[3];
    const long long BTC = in_sizes[5];

    static bool attr_done = false;
    if (!attr_done) {
        cudaFuncSetAttribute(wkv_warpscan_kernel,
                             cudaFuncAttributeMaxDynamicSharedMemorySize,
                             SMEM_BYTES);
        attr_done = true;
    }

    wkv_warpscan_kernel<<<GRID, THREADS, SMEM_BYTES>>>(
        seqlen_p, td, tf, k, v, out, C, BTC);
}

// round 12
// speedup vs baseline: 1.0325x; 1.0325x over previous
#include <cuda_runtime.h>
#include <cstdint>

// WKV (RWKV v4) — warp-parallel weighted scan over T, single pass
// (k,v read once, y written once = 192 MB floor), with 16-byte L1 ops.
//
//   state_t = lam*state_{t-1} + e^{k_t}(v_t, 1),  lam = exp(-exp(td[c]))
//   y_t = (A_{t-1} + e^u e^{k_t} v_t) / (B_{t-1} + e^u e^{k_t})
//
// lam is per-channel constant -> the decayed prefix is a Kogge-Stone scan
// with lane-uniform weights lam^{2^j} (5 shfl levels x 2 fma).
//   A_pre(l) = lam^l * S + excl(l);   S' = lam^32 * S + incl(31)
//
// Block = 512 thr = 16 warps = 16 channels x full T; warp = channel,
// lane = timestep. Tiles 128t x 16c in smem, ROW STRIDE 20 floats (80 B):
// every 16B chunk is 16B-aligned -> cp.async.16 loads (4x fewer L1 ops than
// R11's 4B loads, which were the measured bottleneck at L1=69.5%), and the
// y flush is LDS.128 + st.global.cs.v4. Column reads (stride 20) hit 8
// banks -> 4-way conflicts, costed and acceptable.

constexpr int CPB     = 16;          // channels per block == warps
constexpr int TS      = 128;         // timesteps per tile
constexpr int STR     = 20;          // smem row stride in floats (80 B)
constexpr int THREADS = CPB * 32;    // 512
constexpr int GRID    = 1024;
constexpr int TILE_F  = TS * STR;    // floats per tile buffer
// smem: k[2] | v[2] | y[2]
constexpr int SMEM_BYTES = 6 * TILE_F * (int)sizeof(float);  // 61440 B

__device__ __forceinline__ void cpasync16(float* s, const float* g) {
    unsigned sa = (unsigned)__cvta_generic_to_shared(s);
    asm volatile("cp.async.cg.shared.global [%0], [%1], 16;\n"
                 :: "r"(sa), "l"(g) : "memory");
}

__device__ __forceinline__ void stcs4(float* p, float x, float y,
                                      float z, float w) {
    asm volatile("st.global.cs.v4.f32 [%0], {%1, %2, %3, %4};\n"
                 :: "l"(p), "f"(x), "f"(y), "f"(z), "f"(w) : "memory");
}

__device__ __forceinline__ void stcs(float* p, float v) {
    asm volatile("st.global.cs.f32 [%0], %1;\n" :: "l"(p), "f"(v) : "memory");
}

__device__ __forceinline__ int read_dim(const void* p) {
    int i = *reinterpret_cast<const int*>(p);
    if (i >= 1 && i <= (1 << 20)) return i;
    float f = *reinterpret_cast<const float*>(p);
    int fi = (int)f;
    return (fi >= 1) ? fi : 1;
}

__global__ __launch_bounds__(THREADS, 2)
void wkv_warpscan_kernel(const void* __restrict__ seqlen_p,
                         const float* __restrict__ td,
                         const float* __restrict__ tf,
                         const float* __restrict__ kg,
                         const float* __restrict__ vg,
                         float* __restrict__ out,
                         int C, long long BTC)
{
    extern __shared__ float smem[];
    float* sk = smem;                 // [2][TILE_F]
    float* sv = smem + 2 * TILE_F;
    float* sy = smem + 4 * TILE_F;

    const int tid  = threadIdx.x;
    const int w    = tid >> 5;        // warp == local channel
    const int lane = tid & 31;

    const int T = read_dim(seqlen_p);
    const long long BT = BTC / C;
    const int B = (int)(BT / T);
    const int ctiles = (C + CPB - 1) / CPB;
    const int nrows  = B * ctiles;
    const int ntiles = (T + TS - 1) / TS;
    const unsigned FULL = 0xffffffffu;

    // chunk mapping for loads/flush: thread -> (t row, 4-channel group)
    const int lt = tid >> 2;          // 0..127
    const int cg = tid & 3;           // 0..3

    const bool vec_ok = ((C & 15) == 0) &&
                        ((((uintptr_t)kg)  & 15) == 0) &&
                        ((((uintptr_t)vg)  & 15) == 0) &&
                        ((((uintptr_t)out) & 15) == 0);

    for (int row = blockIdx.x; row < nrows; row += gridDim.x) {
        const int b  = row / ctiles;
        const int c0 = (row % ctiles) * CPB;
        const float* kb = kg + (long long)b * T * C;
        const float* vb = vg + (long long)b * T * C;
        float* ob = out + (long long)b * T * C;

        const int  c      = c0 + w;
        const bool cvalid = (c < C);
        const float ew  = cvalid ? __expf(td[c]) : 0.f;   // e^{td}
        const float eu  = cvalid ? __expf(tf[c]) : 0.f;   // e^{tf}
        const float lam = __expf(-ew);                    // exp(-e^{td})
        const float lam2  = lam  * lam;
        const float lam4  = lam2 * lam2;
        const float lam8  = lam4 * lam4;
        const float lam16 = lam8 * lam8;
        const float lam32 = lam16 * lam16;
        const float lamlane = __expf(-(float)lane * ew);  // lam^lane

        float SA = 0.f, SB = 0.f;                         // running seed

        auto load_tile = [&](int ti) {
            if (ti < ntiles) {
                const int buf = ti & 1;
                int gt = ti * TS + lt;
                if (gt >= T) gt = T - 1;                  // clamp tail
                float* dk = &sk[buf * TILE_F + lt * STR + cg * 4];
                float* dv = &sv[buf * TILE_F + lt * STR + cg * 4];
                if (vec_ok) {
                    const long long go = (long long)gt * C + c0 + cg * 4;
                    cpasync16(dk, kb + go);
                    cpasync16(dv, vb + go);
                } else {
                    #pragma unroll
                    for (int i = 0; i < 4; ++i) {
                        const int gc = c0 + cg * 4 + i;
                        const float kv = (gc < C) ? kb[(long long)gt * C + gc] : 0.f;
                        const float vv = (gc < C) ? vb[(long long)gt * C + gc] : 0.f;
                        dk[i] = kv; dv[i] = vv;
                    }
                }
            }
            asm volatile("cp.async.commit_group;\n" ::);
        };

        load_tile(0);
        load_tile(1);

        for (int ti = 0; ti < ntiles; ++ti) {
            const int buf = ti & 1;
            asm volatile("cp.async.wait_group 1;\n" ::);
            __syncthreads();

            const float* tk = &sk[buf * TILE_F];
            const float* tv = &sv[buf * TILE_F];
            float*       ty = &sy[buf * TILE_F];
            const int t0    = ti * TS;
            const int steps = min(TS, T - t0);

            #pragma unroll
            for (int m = 0; m < TS / 32; ++m) {
                if (m * 32 < steps) {            // warp-uniform
                    const int t = m * 32 + lane;
                    const bool tvld = (t0 + t) < T;
                    const float kt = tk[t * STR + w];
                    const float vt = tv[t * STR + w];
                    const float ek = tvld ? __expf(kt) : 0.f;
                    float uA = ek * vt;
                    float uB = ek;

                    // Weighted Kogge-Stone inclusive scan.
                    float a, bsh;
                    a   = __shfl_up_sync(FULL, uA, 1);
                    bsh = __shfl_up_sync(FULL, uB, 1);
                    if (lane >= 1)  { uA = fmaf(lam,   a, uA); uB = fmaf(lam,   bsh, uB); }
                    a   = __shfl_up_sync(FULL, uA, 2);
                    bsh = __shfl_up_sync(FULL, uB, 2);
                    if (lane >= 2)  { uA = fmaf(lam2,  a, uA); uB = fmaf(lam2,  bsh, uB); }
                    a   = __shfl_up_sync(FULL, uA, 4);
                    bsh = __shfl_up_sync(FULL, uB, 4);
                    if (lane >= 4)  { uA = fmaf(lam4,  a, uA); uB = fmaf(lam4,  bsh, uB); }
                    a   = __shfl_up_sync(FULL, uA, 8);
                    bsh = __shfl_up_sync(FULL, uB, 8);
                    if (lane >= 8)  { uA = fmaf(lam8,  a, uA); uB = fmaf(lam8,  bsh, uB); }
                    a   = __shfl_up_sync(FULL, uA, 16);
                    bsh = __shfl_up_sync(FULL, uB, 16);
                    if (lane >= 16) { uA = fmaf(lam16, a, uA); uB = fmaf(lam16, bsh, uB); }

                    // Exclusive prefix + decayed seed.
                    float Aex = __shfl_up_sync(FULL, uA, 1);
                    float Bex = __shfl_up_sync(FULL, uB, 1);
                    if (lane == 0) { Aex = 0.f; Bex = 0.f; }
                    const float Apre = fmaf(lamlane, SA, Aex);
                    const float Bpre = fmaf(lamlane, SB, Bex);

                    const float eku = eu * ek;
                    const float y = __fdividef(fmaf(eku, vt, Apre), Bpre + eku);
                    ty[t * STR + w] = y;

                    // Seed for next chunk.
                    const float LA = __shfl_sync(FULL, uA, 31);
                    const float LB = __shfl_sync(FULL, uB, 31);
                    SA = fmaf(lam32, SA, LA);
                    SB = fmaf(lam32, SB, LB);
                }
            }
            __syncthreads();     // y staged, tile buffers consumable

            load_tile(ti + 2);   // refill the buffer just consumed

            // Vectorized flush of staged y: LDS.128 + st.global.cs.v4.
            {
                const int gt = t0 + lt;
                if (gt < T) {
                    const float4 yv =
                        *reinterpret_cast<const float4*>(&ty[lt * STR + cg * 4]);
                    const int gc = c0 + cg * 4;
                    if (vec_ok) {
                        stcs4(ob + (long long)gt * C + gc, yv.x, yv.y, yv.z, yv.w);
                    } else {
                        if (gc + 0 < C) stcs(ob + (long long)gt * C + gc + 0, yv.x);
                        if (gc + 1 < C) stcs(ob + (long long)gt * C + gc + 1, yv.y);
                        if (gc + 2 < C) stcs(ob + (long long)gt * C + gc + 2, yv.z);
                        if (gc + 3 < C) stcs(ob + (long long)gt * C + gc + 3, yv.w);
                    }
                }
            }
        }
        asm volatile("cp.async.wait_group 0;\n" ::);
        __syncthreads();
    }
}

extern "C" void kernel_launch(void* const* d_in, const int* in_sizes, int n_in,
                              void* d_out, int out_size)
{
    // metadata order: batch_size, seq_len, embedding_dim, time_decay,
    //                 time_first, k, v
    const void*  seqlen_p = d_in[1];
    const float* td = (const float*)d_in[3];
    const float* tf = (const float*)d_in[4];
    const float* k  = (const float*)d_in[5];
    const float* v  = (const float*)d_in[6];
    float* out = (float*)d_out;

    const int C = in_sizes[3];
    const long long BTC = in_sizes[5];

    static bool attr_done = false;
    if (!attr_done) {
        cudaFuncSetAttribute(wkv_warpscan_kernel,
                             cudaFuncAttributeMaxDynamicSharedMemorySize,
                             SMEM_BYTES);
        attr_done = true;
    }

    wkv_warpscan_kernel<<<GRID, THREADS, SMEM_BYTES>>>(
        seqlen_p, td, tf, k, v, out, C, BTC);
}

// round 13
// speedup vs baseline: 1.2646x; 1.2248x over previous
#include <cuda_runtime.h>
#include <cstdint>

// WKV (RWKV v4) — warp-parallel weighted scan, thread-serial-4 variant.
// Single pass: k,v read once, y written once (192 MB = traffic floor).
//
//   state_t = lam*state_{t-1} + e^{k_t}(v_t, 1),  lam = exp(-exp(td[c]))
//   y_t = (A_{t-1} + e^u e^{k_t} v_t) / (B_{t-1} + e^u e^{k_t})
//
// Mapping: block = 512 thr = 16 warps = 16 channels; warp = channel; each
// thread owns 4 CONSECUTIVE timesteps; warp covers 128 t per tile.
// smem is CHANNEL-MAJOR [16][132]: the scan's k/v reads are single LDS.128
// (16B/lane, conflict-free) and y staging is one STS.128 — the scalar
// (2-way-conflicted) ops survive only in the global<->smem transpose
// (4 STS on load, 4 LDS on flush). R12's measured L1-wavefront bottleneck
// (scalar 4-way-conflicted scan reads / y stores) is gone.
// Scan: thread-local inclusive (3 fma/array) + Kogge-Stone over lanes with
// weight lam^4 (5 levels) + re-serialized 4-step emit. Loads are LDG.128 ->
// registers -> STS, software-pipelined 2 tiles ahead.

constexpr int CPB     = 16;           // channels per block == warps
constexpr int TS      = 128;          // timesteps per tile
constexpr int STR     = 132;          // floats per channel row (16B-aligned)
constexpr int THREADS = 512;
constexpr int GRID    = 1024;
constexpr int ARR_F   = CPB * STR;    // floats per array buffer
// smem: k[2] | v[2] | y[1]
constexpr int SMEM_BYTES = 5 * ARR_F * (int)sizeof(float);  // 42240 B

__device__ __forceinline__ void stcs4(float* p, float4 v) {
    asm volatile("st.global.cs.v4.f32 [%0], {%1, %2, %3, %4};\n"
                 :: "l"(p), "f"(v.x), "f"(v.y), "f"(v.z), "f"(v.w) : "memory");
}
__device__ __forceinline__ void stcs(float* p, float v) {
    asm volatile("st.global.cs.f32 [%0], %1;\n" :: "l"(p), "f"(v) : "memory");
}
__device__ __forceinline__ float4 ldcs4(const float* p) {
    float4 v;
    asm volatile("ld.global.cs.v4.f32 {%0, %1, %2, %3}, [%4];\n"
                 : "=f"(v.x), "=f"(v.y), "=f"(v.z), "=f"(v.w) : "l"(p));
    return v;
}

__device__ __forceinline__ int read_dim(const void* p) {
    int i = *reinterpret_cast<const int*>(p);
    if (i >= 1 && i <= (1 << 20)) return i;
    float f = *reinterpret_cast<const float*>(p);
    int fi = (int)f;
    return (fi >= 1) ? fi : 1;
}

__global__ __launch_bounds__(THREADS, 2)
void wkv_warpscan_kernel(const void* __restrict__ seqlen_p,
                         const float* __restrict__ td,
                         const float* __restrict__ tf,
                         const float* __restrict__ kg,
                         const float* __restrict__ vg,
                         float* __restrict__ out,
                         int C, long long BTC)
{
    extern __shared__ float smem[];
    float* skb[2] = { smem,              smem + ARR_F };
    float* svb[2] = { smem + 2 * ARR_F,  smem + 3 * ARR_F };
    float* sy     =   smem + 4 * ARR_F;

    const int tid  = threadIdx.x;
    const int w    = tid >> 5;        // warp == local channel
    const int lane = tid & 31;
    const int lt   = tid >> 2;        // 0..127 : timestep row for ld/st
    const int cg   = tid & 3;         // 0..3   : 4-channel group

    const int T = read_dim(seqlen_p);
    const long long BT = BTC / C;
    const int B = (int)(BT / T);
    const int ctiles = (C + CPB - 1) / CPB;
    const int nrows  = B * ctiles;
    const int ntiles = (T + TS - 1) / TS;
    const unsigned FULL = 0xffffffffu;

    const bool vec_ok = ((C & 15) == 0) &&
                        ((((uintptr_t)kg)  & 15) == 0) &&
                        ((((uintptr_t)vg)  & 15) == 0) &&
                        ((((uintptr_t)out) & 15) == 0);

    for (int row = blockIdx.x; row < nrows; row += gridDim.x) {
        const int b  = row / ctiles;
        const int c0 = (row % ctiles) * CPB;
        const float* kb = kg + (long long)b * T * C;
        const float* vb = vg + (long long)b * T * C;
        float* ob = out + (long long)b * T * C;

        const int  c      = c0 + w;
        const bool cvalid = (c < C);
        const float ew  = cvalid ? __expf(td[c]) : 0.f;   // e^{td}
        const float eu  = cvalid ? __expf(tf[c]) : 0.f;   // e^{tf}
        const float lam = __expf(-ew);                    // exp(-e^{td})
        const float l2   = lam * lam;
        const float lam4 = l2 * l2;                       // KS base weight
        const float w1 = lam4, w2 = w1 * w1, w4 = w2 * w2,
                    w8 = w4 * w4, w16 = w8 * w8;
        const float lam128 = w16 * w16;                   // lam^128
        const float lam4lane = __expf(-4.f * (float)lane * ew);  // lam^{4lane}

        float SA = 0.f, SB = 0.f;                         // running seed

        float4 kR, vR;                                    // staged next tile

        auto ldg_tile = [&](int ti) {
            int gt = ti * TS + lt; if (gt >= T) gt = T - 1;
            if (vec_ok) {
                const long long go = (long long)gt * C + c0 + cg * 4;
                kR = ldcs4(kb + go);
                vR = ldcs4(vb + go);
            } else {
                float kk[4], vv[4];
                #pragma unroll
                for (int i = 0; i < 4; ++i) {
                    const int gc = c0 + cg * 4 + i;
                    kk[i] = (gc < C) ? kb[(long long)gt * C + gc] : 0.f;
                    vv[i] = (gc < C) ? vb[(long long)gt * C + gc] : 0.f;
                }
                kR = make_float4(kk[0], kk[1], kk[2], kk[3]);
                vR = make_float4(vv[0], vv[1], vv[2], vv[3]);
            }
        };
        auto sts_tile = [&](int buf) {  // transpose registers -> [c][t]
            float* dk = skb[buf];
            float* dv = svb[buf];
            dk[(cg * 4 + 0) * STR + lt] = kR.x;
            dk[(cg * 4 + 1) * STR + lt] = kR.y;
            dk[(cg * 4 + 2) * STR + lt] = kR.z;
            dk[(cg * 4 + 3) * STR + lt] = kR.w;
            dv[(cg * 4 + 0) * STR + lt] = vR.x;
            dv[(cg * 4 + 1) * STR + lt] = vR.y;
            dv[(cg * 4 + 2) * STR + lt] = vR.z;
            dv[(cg * 4 + 3) * STR + lt] = vR.w;
        };

        // ---- prolog: fill buffer 0, stage tile 1 in registers ----
        ldg_tile(0);
        sts_tile(0);
        if (ntiles > 1) ldg_tile(1);
        __syncthreads();

        for (int ti = 0; ti < ntiles; ++ti) {
            const int buf = ti & 1;
            const int t0  = ti * TS;

            // ---- scan: one LDS.128 per array, conflict-free ----
            const float* tk = skb[buf] + w * STR + 4 * lane;
            const float* tv = svb[buf] + w * STR + 4 * lane;
            const float4 kq = *reinterpret_cast<const float4*>(tk);
            const float4 vq = *reinterpret_cast<const float4*>(tv);

            const int tg = t0 + 4 * lane;
            const float ek0 = (tg + 0 < T) ? __expf(kq.x) : 0.f;
            const float ek1 = (tg + 1 < T) ? __expf(kq.y) : 0.f;
            const float ek2 = (tg + 2 < T) ? __expf(kq.z) : 0.f;
            const float ek3 = (tg + 3 < T) ? __expf(kq.w) : 0.f;
            const float uA0 = ek0 * vq.x, uA1 = ek1 * vq.y;
            const float uA2 = ek2 * vq.z, uA3 = ek3 * vq.w;

            // Thread-local inclusive totals (4 steps).
            float IA = uA0, IB = ek0;
            IA = fmaf(lam, IA, uA1);  IB = fmaf(lam, IB, ek1);
            IA = fmaf(lam, IA, uA2);  IB = fmaf(lam, IB, ek2);
            IA = fmaf(lam, IA, uA3);  IB = fmaf(lam, IB, ek3);

            // Kogge-Stone over lanes, weight lam^4.
            float a, bb;
            a = __shfl_up_sync(FULL, IA, 1);  bb = __shfl_up_sync(FULL, IB, 1);
            if (lane >= 1)  { IA = fmaf(w1,  a, IA); IB = fmaf(w1,  bb, IB); }
            a = __shfl_up_sync(FULL, IA, 2);  bb = __shfl_up_sync(FULL, IB, 2);
            if (lane >= 2)  { IA = fmaf(w2,  a, IA); IB = fmaf(w2,  bb, IB); }
            a = __shfl_up_sync(FULL, IA, 4);  bb = __shfl_up_sync(FULL, IB, 4);
            if (lane >= 4)  { IA = fmaf(w4,  a, IA); IB = fmaf(w4,  bb, IB); }
            a = __shfl_up_sync(FULL, IA, 8);  bb = __shfl_up_sync(FULL, IB, 8);
            if (lane >= 8)  { IA = fmaf(w8,  a, IA); IB = fmaf(w8,  bb, IB); }
            a = __shfl_up_sync(FULL, IA, 16); bb = __shfl_up_sync(FULL, IB, 16);
            if (lane >= 16) { IA = fmaf(w16, a, IA); IB = fmaf(w16, bb, IB); }

            float EA = __shfl_up_sync(FULL, IA, 1);
            float EB = __shfl_up_sync(FULL, IB, 1);
            if (lane == 0) { EA = 0.f; EB = 0.f; }

            // State just before this thread's first element.
            float stA = fmaf(lam4lane, SA, EA);
            float stB = fmaf(lam4lane, SB, EB);

            // Re-serialized emit of 4 timesteps.
            float4 yq;
            float eku;
            eku  = eu * ek0;
            yq.x = __fdividef(fmaf(eku, vq.x, stA), stB + eku);
            stA  = fmaf(lam, stA, uA0);  stB = fmaf(lam, stB, ek0);
            eku  = eu * ek1;
            yq.y = __fdividef(fmaf(eku, vq.y, stA), stB + eku);
            stA  = fmaf(lam, stA, uA1);  stB = fmaf(lam, stB, ek1);
            eku  = eu * ek2;
            yq.z = __fdividef(fmaf(eku, vq.z, stA), stB + eku);
            stA  = fmaf(lam, stA, uA2);  stB = fmaf(lam, stB, ek2);
            eku  = eu * ek3;
            yq.w = __fdividef(fmaf(eku, vq.w, stA), stB + eku);

            // Stage y: one STS.128, conflict-free.
            *reinterpret_cast<float4*>(sy + w * STR + 4 * lane) = yq;

            // Next-chunk seed from lane 31's inclusive totals.
            const float LA = __shfl_sync(FULL, IA, 31);
            const float LB = __shfl_sync(FULL, IB, 31);
            SA = fmaf(lam128, SA, LA);
            SB = fmaf(lam128, SB, LB);

            // ---- fill next buffer from registers, fetch tile+2 ----
            if (ti + 1 < ntiles) sts_tile((ti + 1) & 1);
            if (ti + 2 < ntiles) ldg_tile(ti + 2);
            __syncthreads();        // y staged + next k/v buffer complete

            // ---- flush y: gather [c][t] -> [t][c], STG.128 ----
            const int gt = t0 + lt;
            if (gt < T) {
                float4 yo;
                yo.x = sy[(cg * 4 + 0) * STR + lt];
                yo.y = sy[(cg * 4 + 1) * STR + lt];
                yo.z = sy[(cg * 4 + 2) * STR + lt];
                yo.w = sy[(cg * 4 + 3) * STR + lt];
                const int gc = c0 + cg * 4;
                if (vec_ok) {
                    stcs4(ob + (long long)gt * C + gc, yo);
                } else {
                    if (gc + 0 < C) stcs(ob + (long long)gt * C + gc + 0, yo.x);
                    if (gc + 1 < C) stcs(ob + (long long)gt * C + gc + 1, yo.y);
                    if (gc + 2 < C) stcs(ob + (long long)gt * C + gc + 2, yo.z);
                    if (gc + 3 < C) stcs(ob + (long long)gt * C + gc + 3, yo.w);
                }
            }
            __syncthreads();        // sy free for next iteration
        }
    }
}

extern "C" void kernel_launch(void* const* d_in, const int* in_sizes, int n_in,
                              void* d_out, int out_size)
{
    // metadata order: batch_size, seq_len, embedding_dim, time_decay,
    //                 time_first, k, v
    const void*  seqlen_p = d_in[1];
    const float* td = (const float*)d_in[3];
    const float* tf = (const float*)d_in[4];
    const float* k  = (const float*)d_in[5];
    const float* v  = (const float*)d_in[6];
    float* out = (float*)d_out;

    const int C = in_sizes[3];
    const long long BTC = in_sizes[5];

    static bool attr_done = false;
    if (!attr_done) {
        cudaFuncSetAttribute(wkv_warpscan_kernel,
                             cudaFuncAttributeMaxDynamicSharedMemorySize,
                             SMEM_BYTES);
        attr_done = true;
    }

    wkv_warpscan_kernel<<<GRID, THREADS, SMEM_BYTES>>>(
        seqlen_p, td, tf, k, v, out, C, BTC);
}